// round 5
// baseline (speedup 1.0000x reference)
#include <cuda_runtime.h>
#include <cuda_bf16.h>

#define NN   20000
#define EE   200000
#define IND  500
#define HD   256
#define OD   16
#define MHD  64

// -------- scratch (alloc-free rule: __device__ globals) --------
__device__ float g_t1[NN * 64];        // MLP hidden
__device__ float g_h [NN * HD];        // h, then xb (mutated in place)
__device__ float g_H [NN * HD];        // sheaf-transformed H per layer
__device__ float g_LH[NN * HD];        // scatter accumulator
__device__ float g_Fs[EE * 16];
__device__ float g_Ft[EE * 16];
__device__ float g_WaT[HD * 64];       // Wm1[:, :256] transposed -> [k][j]
__device__ float g_WbT[HD * 64];       // Wm1[:, 256:] transposed
__device__ float g_Wd2T[2 * 64 * 64];  // Wd2[l] transposed -> [f][g]

// -------- weight pre-transposes --------
__global__ void prep_kernel(const float* __restrict__ Wm1,
                            const float* __restrict__ Wd2) {
    int i = blockIdx.x * blockDim.x + threadIdx.x;
    if (i < 256 * 64) {
        int k = i / 64, j = i % 64;
        g_WaT[i] = Wm1[j * 512 + k];
        g_WbT[i] = Wm1[j * 512 + 256 + k];
    }
    if (i < 2 * 64 * 64) {
        int l = i / 4096, r = i % 4096;
        int f = r / 64, g = r % 64;
        g_Wd2T[i] = Wd2[l * 4096 + g * 64 + f];
    }
}

// -------- generic C = act(A @ W^T + b), A[M,Kd], W[Nc,Kd] --------
__global__ void sgemm_bias(const float* __restrict__ A,
                           const float* __restrict__ W,
                           const float* __restrict__ bias,
                           float* __restrict__ C,
                           int M, int Kd, int Nc, int doRelu) {
    __shared__ float As[16][65];
    __shared__ float Bs[16][65];
    int t  = threadIdx.x;
    int tx = t & 15, ty = t >> 4;
    int m0 = blockIdx.y * 64, n0 = blockIdx.x * 64;
    float acc[4][4];
#pragma unroll
    for (int i = 0; i < 4; i++)
#pragma unroll
        for (int j = 0; j < 4; j++) acc[i][j] = 0.f;

    for (int k0 = 0; k0 < Kd; k0 += 16) {
#pragma unroll
        for (int i = 0; i < 4; i++) {
            int q  = t + i * 256;
            int kk = q & 15, mm = q >> 4;
            int m = m0 + mm, k = k0 + kk;
            As[kk][mm] = (m < M && k < Kd) ? A[(size_t)m * Kd + k] : 0.f;
            int n = n0 + mm;
            Bs[kk][mm] = (n < Nc && k < Kd) ? W[(size_t)n * Kd + k] : 0.f;
        }
        __syncthreads();
#pragma unroll
        for (int kk = 0; kk < 16; kk++) {
            float a[4], b[4];
#pragma unroll
            for (int i = 0; i < 4; i++) { a[i] = As[kk][ty * 4 + i]; b[i] = Bs[kk][tx * 4 + i]; }
#pragma unroll
            for (int i = 0; i < 4; i++)
#pragma unroll
                for (int j = 0; j < 4; j++) acc[i][j] += a[i] * b[j];
        }
        __syncthreads();
    }
#pragma unroll
    for (int i = 0; i < 4; i++) {
        int m = m0 + ty * 4 + i;
        if (m >= M) continue;
#pragma unroll
        for (int j = 0; j < 4; j++) {
            int n = n0 + tx * 4 + j;
            if (n >= Nc) continue;
            float v = acc[i][j] + bias[n];
            if (doRelu) v = fmaxf(v, 0.f);
            C[(size_t)m * Nc + n] = v;
        }
    }
}

// -------- edge MLP: Fs/Ft from gathered h[src], h[dst] --------
// 8 edges/block, 256 threads. thread: j = t&63 hidden unit, handles 2 edges.
__global__ void edge_mlp_kernel(const int* __restrict__ ei,
                                const float* __restrict__ bm1,
                                const float* __restrict__ Wm2,
                                const float* __restrict__ bm2) {
    __shared__ float sh[8][512];   // [edge][0:256]=h[src], [256:512]=h[dst]
    int t   = threadIdx.x;
    int eb  = blockIdx.x * 8;
    float4* sh4 = (float4*)sh;
    const float4* h4 = (const float4*)g_h;
    for (int q = t; q < 8 * 128; q += 256) {
        int e_loc = q >> 7, v = q & 127;
        int edge  = eb + e_loc;
        int node  = (v < 64) ? ei[edge] : ei[EE + edge];
        sh4[e_loc * 128 + v] = h4[(size_t)node * 64 + (v & 63)];
    }
    __syncthreads();

    int j = t & 63, g = t >> 6;
    int ea = g * 2, ebv = g * 2 + 1;
    float u1a = 0.f, u2a = 0.f, u1b = 0.f, u2b = 0.f;
#pragma unroll 4
    for (int k = 0; k < 256; k++) {
        float wa = g_WaT[k * 64 + j];
        float wb = g_WbT[k * 64 + j];
        float sa = sh[ea][k],  da = sh[ea][256 + k];
        float sb = sh[ebv][k], db = sh[ebv][256 + k];
        u1a += wa * sa; u1a += wb * da;
        u2a += wa * da; u2a += wb * sa;
        u1b += wa * sb; u1b += wb * db;
        u2b += wa * db; u2b += wb * sb;
    }
    float b1 = bm1[j];
    u1a = fmaxf(u1a + b1, 0.f); u2a = fmaxf(u2a + b1, 0.f);
    u1b = fmaxf(u1b + b1, 0.f); u2b = fmaxf(u2b + b1, 0.f);
    __syncthreads();
    sh[ea][j]       = u1a; sh[ea][64 + j]  = u2a;
    sh[ebv][j]      = u1b; sh[ebv][64 + j] = u2b;
    __syncthreads();

    // project to 16 outputs: 8 edges x 16 outs x {Fs,Ft} = 256 dots of len 64
    int e_loc = t >> 5, r = t & 31;
    int o = r & 15, isFt = r >> 4;
    int edge = eb + e_loc;
    const float* mrow = &sh[e_loc][isFt * 64];
    float acc = bm2[o];
#pragma unroll 8
    for (int jj = 0; jj < 64; jj++) acc += Wm2[o * 64 + jj] * mrow[jj];
    if (isFt) g_Ft[edge * 16 + o] = acc;
    else      g_Fs[edge * 16 + o] = acc;
}

// -------- per-node sheaf transform H = (Wd1^T xb) Wd2^T; also zero LH --------
__global__ void sheaf_H_kernel(const float* __restrict__ Wd1, int l) {
    __shared__ float xbs[4][256];
    __shared__ float tmps[4][256];
    int t  = threadIdx.x;
    int nb = blockIdx.x * 4;
    int n_loc = t >> 6, f = t & 63;
    {
        float4* x4 = (float4*)xbs;
        x4[n_loc * 64 + f] = ((const float4*)g_h)[(size_t)(nb + n_loc) * 64 + f];
    }
    __syncthreads();
#pragma unroll
    for (int i = 0; i < 4; i++) {
        float acc = 0.f;
#pragma unroll
        for (int j = 0; j < 4; j++)
            acc += Wd1[l * 16 + j * 4 + i] * xbs[n_loc][j * 64 + f];
        tmps[n_loc][i * 64 + f] = acc;
    }
    __syncthreads();
    int node = nb + n_loc;
    float a0 = 0.f, a1 = 0.f, a2 = 0.f, a3 = 0.f;
#pragma unroll 8
    for (int ff = 0; ff < 64; ff++) {
        float wv = g_Wd2T[l * 4096 + ff * 64 + f];
        a0 += tmps[n_loc][ff] * wv;
        a1 += tmps[n_loc][64 + ff] * wv;
        a2 += tmps[n_loc][128 + ff] * wv;
        a3 += tmps[n_loc][192 + ff] * wv;
    }
    size_t base = (size_t)node * 256;
    g_H[base + f]       = a0;
    g_H[base + 64 + f]  = a1;
    g_H[base + 128 + f] = a2;
    g_H[base + 192 + f] = a3;
    g_LH[base + f] = 0.f; g_LH[base + 64 + f] = 0.f;
    g_LH[base + 128 + f] = 0.f; g_LH[base + 192 + f] = 0.f;
}

// -------- per-edge Bx + scatter into LH --------
// 4 edges/block, 64 threads per edge (thread = f column)
__global__ void edge_scatter_kernel(const int* __restrict__ ei) {
    __shared__ float sF[4][32];   // [edge][0:16]=Fs, [16:32]=Ft
    int t  = threadIdx.x;
    int e0 = blockIdx.x * 4;
    if (t < 128) {
        int e_loc = t >> 5, r = t & 31;
        int edge = e0 + e_loc;
        sF[e_loc][r] = (r < 16) ? g_Fs[edge * 16 + r] : g_Ft[edge * 16 + (r - 16)];
    }
    __syncthreads();
    int e_loc = t >> 6, f = t & 63;
    int edge = e0 + e_loc;
    int s = ei[edge], d = ei[EE + edge];
    size_t sb = (size_t)s * 256, db = (size_t)d * 256;
    float hs[4], hd[4];
#pragma unroll
    for (int j = 0; j < 4; j++) { hs[j] = g_H[sb + j * 64 + f]; hd[j] = g_H[db + j * 64 + f]; }
    float bx[4];
#pragma unroll
    for (int i = 0; i < 4; i++) {
        float a = 0.f;
#pragma unroll
        for (int j = 0; j < 4; j++)
            a += sF[e_loc][16 + i * 4 + j] * hd[j] - sF[e_loc][i * 4 + j] * hs[j];
        bx[i] = a;
    }
#pragma unroll
    for (int j = 0; j < 4; j++) {
        float cs = 0.f, ct = 0.f;
#pragma unroll
        for (int i = 0; i < 4; i++) {
            cs += sF[e_loc][i * 4 + j] * bx[i];
            ct += sF[e_loc][16 + i * 4 + j] * bx[i];
        }
        atomicAdd(&g_LH[sb + j * 64 + f], -cs);
        atomicAdd(&g_LH[db + j * 64 + f],  ct);
    }
}

// -------- xb = xb - relu(LH) --------
__global__ void xb_update_kernel() {
    int i = blockIdx.x * blockDim.x + threadIdx.x;
    if (i < NN * 64) {
        float4 xv = ((float4*)g_h)[i];
        float4 lv = ((float4*)g_LH)[i];
        xv.x -= fmaxf(lv.x, 0.f);
        xv.y -= fmaxf(lv.y, 0.f);
        xv.z -= fmaxf(lv.z, 0.f);
        xv.w -= fmaxf(lv.w, 0.f);
        ((float4*)g_h)[i] = xv;
    }
}

extern "C" void kernel_launch(void* const* d_in, const int* in_sizes, int n_in,
                              void* d_out, int out_size) {
    const float* x    = (const float*)d_in[0];
    const int*   ei   = (const int*)  d_in[1];
    const float* Win1 = (const float*)d_in[2];
    const float* bin1 = (const float*)d_in[3];
    const float* Win2 = (const float*)d_in[4];
    const float* bin2 = (const float*)d_in[5];
    const float* Wm1  = (const float*)d_in[6];
    const float* bm1  = (const float*)d_in[7];
    const float* Wm2  = (const float*)d_in[8];
    const float* bm2  = (const float*)d_in[9];
    const float* Wd1  = (const float*)d_in[10];
    const float* Wd2  = (const float*)d_in[11];
    const float* Wo1  = (const float*)d_in[12];
    const float* bo1  = (const float*)d_in[13];
    const float* Wo2  = (const float*)d_in[14];
    const float* bo2  = (const float*)d_in[15];
    float* out = (float*)d_out;

    void *p_t1, *p_h;
    cudaGetSymbolAddress(&p_t1, g_t1);
    cudaGetSymbolAddress(&p_h,  g_h);
    float* t1 = (float*)p_t1;
    float* h  = (float*)p_h;

    prep_kernel<<<96, 256>>>(Wm1, Wd2);

    // h = relu(x @ Win1^T + bin1) @ Win2^T + bin2
    sgemm_bias<<<dim3(1, 313), 256>>>(x,  Win1, bin1, t1, NN, IND, 64, 1);
    sgemm_bias<<<dim3(4, 313), 256>>>(t1, Win2, bin2, h,  NN, 64, HD, 0);

    // edge messages -> Fs, Ft
    edge_mlp_kernel<<<EE / 8, 256>>>(ei, bm1, Wm2, bm2);

    // sheaf diffusion layers (xb lives in g_h)
    for (int l = 0; l < 2; l++) {
        sheaf_H_kernel<<<NN / 4, 256>>>(Wd1, l);
        edge_scatter_kernel<<<EE / 4, 256>>>(ei);
        xb_update_kernel<<<NN * 64 / 256, 256>>>();
    }

    // output MLP
    sgemm_bias<<<dim3(1, 313), 256>>>(h,  Wo1, bo1, t1,  NN, HD, 64, 1);
    sgemm_bias<<<dim3(1, 313), 256>>>(t1, Wo2, bo2, out, NN, 64, OD, 0);
}

// round 9
// speedup vs baseline: 3.0599x; 3.0599x over previous
#include <cuda_runtime.h>
#include <cuda_bf16.h>

#define NN   20000
#define EE   200000
#define IND  500
#define HD   256
#define OD   16
#define MHD  64

// -------- scratch (alloc-free rule: __device__ globals) --------
__device__ float g_t1[NN * 64];        // MLP hidden
__device__ float g_h [NN * HD];        // h, then xb (mutated in place)
__device__ float g_H [NN * HD];        // sheaf-transformed H per layer
__device__ float g_LH[NN * HD];        // scatter accumulator
__device__ float g_pq[NN * 128];       // [n][0:64]=p=h@Wa^T, [64:128]=q=h@Wb^T
__device__ float g_Fs[EE * 16];
__device__ float g_Ft[EE * 16];
__device__ float g_Wpq[128 * HD];      // rows 0-63 = Wa, rows 64-127 = Wb
__device__ float g_Wd2T[2 * 64 * 64];  // Wd2[l] transposed -> [f][g]
__device__ float g_zero[128];          // zero bias (BSS zero-init, never written)

// -------- weight prep --------
__global__ void prep_kernel(const float* __restrict__ Wm1,
                            const float* __restrict__ Wd2) {
    int i = blockIdx.x * blockDim.x + threadIdx.x;
    if (i < 128 * 256) {
        int r = i >> 8, k = i & 255;
        g_Wpq[i] = (r < 64) ? Wm1[r * 512 + k] : Wm1[(r - 64) * 512 + 256 + k];
    }
    if (i < 2 * 64 * 64) {
        int l = i / 4096, rr = i % 4096;
        int f = rr / 64, g = rr % 64;
        g_Wd2T[i] = Wd2[l * 4096 + g * 64 + f];
    }
}

// -------- generic C = act(A @ W^T + b), A[M,Kd], W[Nc,Kd] --------
__global__ void sgemm_bias(const float* __restrict__ A,
                           const float* __restrict__ W,
                           const float* __restrict__ bias,
                           float* __restrict__ C,
                           int M, int Kd, int Nc, int doRelu) {
    __shared__ float As[16][65];
    __shared__ float Bs[16][65];
    int t  = threadIdx.x;
    int tx = t & 15, ty = t >> 4;
    int m0 = blockIdx.y * 64, n0 = blockIdx.x * 64;
    float acc[4][4];
#pragma unroll
    for (int i = 0; i < 4; i++)
#pragma unroll
        for (int j = 0; j < 4; j++) acc[i][j] = 0.f;

    for (int k0 = 0; k0 < Kd; k0 += 16) {
#pragma unroll
        for (int i = 0; i < 4; i++) {
            int q  = t + i * 256;
            int kk = q & 15, mm = q >> 4;
            int m = m0 + mm, k = k0 + kk;
            As[kk][mm] = (m < M && k < Kd) ? A[(size_t)m * Kd + k] : 0.f;
            int n = n0 + mm;
            Bs[kk][mm] = (n < Nc && k < Kd) ? W[(size_t)n * Kd + k] : 0.f;
        }
        __syncthreads();
#pragma unroll
        for (int kk = 0; kk < 16; kk++) {
            float a[4], b[4];
#pragma unroll
            for (int i = 0; i < 4; i++) { a[i] = As[kk][ty * 4 + i]; b[i] = Bs[kk][tx * 4 + i]; }
#pragma unroll
            for (int i = 0; i < 4; i++)
#pragma unroll
                for (int j = 0; j < 4; j++) acc[i][j] += a[i] * b[j];
        }
        __syncthreads();
    }
#pragma unroll
    for (int i = 0; i < 4; i++) {
        int m = m0 + ty * 4 + i;
        if (m >= M) continue;
#pragma unroll
        for (int j = 0; j < 4; j++) {
            int n = n0 + tx * 4 + j;
            if (n >= Nc) continue;
            float v = acc[i][j] + bias[n];
            if (doRelu) v = fmaxf(v, 0.f);
            C[(size_t)m * Nc + n] = v;
        }
    }
}

// -------- fused edge messages: gather pq, relu-add, project with Wm2 --------
// 8 edges/block (16 messages), 256 threads.
__global__ void edge_fused_kernel(const int* __restrict__ ei,
                                  const float* __restrict__ bm1,
                                  const float* __restrict__ Wm2,
                                  const float* __restrict__ bm2) {
    __shared__ float sm[16][68];   // relu'd message pre-activations (padded)
    __shared__ float sW[16][65];   // Wm2 (16x64, padded)
    int t  = threadIdx.x;
    int eb = blockIdx.x * 8;

    // stage Wm2 in smem
#pragma unroll
    for (int q = t; q < 16 * 64; q += 256) {
        sW[q >> 6][q & 63] = Wm2[q];
    }

    // gather + add + bias + relu: 16 msgs x 16 float4 = 256 tasks
    {
        int msg = t >> 4, v = t & 15;
        int edge = eb + (msg >> 1);
        int second = msg & 1;
        int s = ei[edge], d = ei[EE + edge];
        int na = second ? d : s;   // p-row
        int nb = second ? s : d;   // q-row
        const float4* pq4 = (const float4*)g_pq;
        float4 pa = pq4[(size_t)na * 32 + v];
        float4 qb = pq4[(size_t)nb * 32 + 16 + v];
        float4 bb = ((const float4*)bm1)[v];
        sm[msg][v * 4 + 0] = fmaxf(pa.x + qb.x + bb.x, 0.f);
        sm[msg][v * 4 + 1] = fmaxf(pa.y + qb.y + bb.y, 0.f);
        sm[msg][v * 4 + 2] = fmaxf(pa.z + qb.z + bb.z, 0.f);
        sm[msg][v * 4 + 3] = fmaxf(pa.w + qb.w + bb.w, 0.f);
    }
    __syncthreads();

    // projection: 16 msgs x 16 outs = 256 dots of length 64
    {
        int msg = t >> 4, o = t & 15;
        float acc = bm2[o];
#pragma unroll
        for (int jj = 0; jj < 64; jj++)
            acc += sW[o][jj] * sm[msg][jj];
        int edge = eb + (msg >> 1);
        if (msg & 1) g_Ft[edge * 16 + o] = acc;
        else         g_Fs[edge * 16 + o] = acc;
    }
}

// -------- per-node sheaf transform H = (Wd1^T xb) Wd2^T; also zero LH --------
__global__ void sheaf_H_kernel(const float* __restrict__ Wd1, int l) {
    __shared__ float xbs[4][256];
    __shared__ float tmps[4][256];
    int t  = threadIdx.x;
    int nb = blockIdx.x * 4;
    int n_loc = t >> 6, f = t & 63;
    {
        float4* x4 = (float4*)xbs;
        x4[n_loc * 64 + f] = ((const float4*)g_h)[(size_t)(nb + n_loc) * 64 + f];
    }
    __syncthreads();
#pragma unroll
    for (int i = 0; i < 4; i++) {
        float acc = 0.f;
#pragma unroll
        for (int j = 0; j < 4; j++)
            acc += Wd1[l * 16 + j * 4 + i] * xbs[n_loc][j * 64 + f];
        tmps[n_loc][i * 64 + f] = acc;
    }
    __syncthreads();
    int node = nb + n_loc;
    float a0 = 0.f, a1 = 0.f, a2 = 0.f, a3 = 0.f;
#pragma unroll 8
    for (int ff = 0; ff < 64; ff++) {
        float wv = g_Wd2T[l * 4096 + ff * 64 + f];
        a0 += tmps[n_loc][ff] * wv;
        a1 += tmps[n_loc][64 + ff] * wv;
        a2 += tmps[n_loc][128 + ff] * wv;
        a3 += tmps[n_loc][192 + ff] * wv;
    }
    size_t base = (size_t)node * 256;
    g_H[base + f]       = a0;
    g_H[base + 64 + f]  = a1;
    g_H[base + 128 + f] = a2;
    g_H[base + 192 + f] = a3;
    g_LH[base + f] = 0.f; g_LH[base + 64 + f] = 0.f;
    g_LH[base + 128 + f] = 0.f; g_LH[base + 192 + f] = 0.f;
}

// -------- per-edge Bx + scatter into LH --------
__global__ void edge_scatter_kernel(const int* __restrict__ ei) {
    __shared__ float sF[4][32];   // [edge][0:16]=Fs, [16:32]=Ft
    int t  = threadIdx.x;
    int e0 = blockIdx.x * 4;
    if (t < 128) {
        int e_loc = t >> 5, r = t & 31;
        int edge = e0 + e_loc;
        sF[e_loc][r] = (r < 16) ? g_Fs[edge * 16 + r] : g_Ft[edge * 16 + (r - 16)];
    }
    __syncthreads();
    int e_loc = t >> 6, f = t & 63;
    int edge = e0 + e_loc;
    int s = ei[edge], d = ei[EE + edge];
    size_t sb = (size_t)s * 256, db = (size_t)d * 256;
    float hs[4], hd[4];
#pragma unroll
    for (int j = 0; j < 4; j++) { hs[j] = g_H[sb + j * 64 + f]; hd[j] = g_H[db + j * 64 + f]; }
    float bx[4];
#pragma unroll
    for (int i = 0; i < 4; i++) {
        float a = 0.f;
#pragma unroll
        for (int j = 0; j < 4; j++)
            a += sF[e_loc][16 + i * 4 + j] * hd[j] - sF[e_loc][i * 4 + j] * hs[j];
        bx[i] = a;
    }
#pragma unroll
    for (int j = 0; j < 4; j++) {
        float cs = 0.f, ct = 0.f;
#pragma unroll
        for (int i = 0; i < 4; i++) {
            cs += sF[e_loc][i * 4 + j] * bx[i];
            ct += sF[e_loc][16 + i * 4 + j] * bx[i];
        }
        atomicAdd(&g_LH[sb + j * 64 + f], -cs);
        atomicAdd(&g_LH[db + j * 64 + f],  ct);
    }
}

// -------- xb = xb - relu(LH) --------
__global__ void xb_update_kernel() {
    int i = blockIdx.x * blockDim.x + threadIdx.x;
    if (i < NN * 64) {
        float4 xv = ((float4*)g_h)[i];
        float4 lv = ((float4*)g_LH)[i];
        xv.x -= fmaxf(lv.x, 0.f);
        xv.y -= fmaxf(lv.y, 0.f);
        xv.z -= fmaxf(lv.z, 0.f);
        xv.w -= fmaxf(lv.w, 0.f);
        ((float4*)g_h)[i] = xv;
    }
}

extern "C" void kernel_launch(void* const* d_in, const int* in_sizes, int n_in,
                              void* d_out, int out_size) {
    const float* x    = (const float*)d_in[0];
    const int*   ei   = (const int*)  d_in[1];
    const float* Win1 = (const float*)d_in[2];
    const float* bin1 = (const float*)d_in[3];
    const float* Win2 = (const float*)d_in[4];
    const float* bin2 = (const float*)d_in[5];
    const float* Wm1  = (const float*)d_in[6];
    const float* bm1  = (const float*)d_in[7];
    const float* Wm2  = (const float*)d_in[8];
    const float* bm2  = (const float*)d_in[9];
    const float* Wd1  = (const float*)d_in[10];
    const float* Wd2  = (const float*)d_in[11];
    const float* Wo1  = (const float*)d_in[12];
    const float* bo1  = (const float*)d_in[13];
    const float* Wo2  = (const float*)d_in[14];
    const float* bo2  = (const float*)d_in[15];
    float* out = (float*)d_out;

    void *p_t1, *p_h, *p_pq, *p_wpq, *p_zero;
    cudaGetSymbolAddress(&p_t1,   g_t1);
    cudaGetSymbolAddress(&p_h,    g_h);
    cudaGetSymbolAddress(&p_pq,   g_pq);
    cudaGetSymbolAddress(&p_wpq,  g_Wpq);
    cudaGetSymbolAddress(&p_zero, g_zero);
    float* t1   = (float*)p_t1;
    float* h    = (float*)p_h;
    float* pq   = (float*)p_pq;
    float* wpq  = (float*)p_wpq;
    float* zero = (float*)p_zero;

    prep_kernel<<<128, 256>>>(Wm1, Wd2);

    // h = relu(x @ Win1^T + bin1) @ Win2^T + bin2
    sgemm_bias<<<dim3(1, 313), 256>>>(x,  Win1, bin1, t1, NN, IND, 64, 1);
    sgemm_bias<<<dim3(4, 313), 256>>>(t1, Win2, bin2, h,  NN, 64, HD, 0);

    // node projections: pq = h @ [Wa;Wb]^T   (20000 x 128)
    sgemm_bias<<<dim3(2, 313), 256>>>(h, wpq, zero, pq, NN, HD, 128, 0);

    // edge messages -> Fs, Ft  (gather p/q rows from L2-resident pq)
    edge_fused_kernel<<<EE / 8, 256>>>(ei, bm1, Wm2, bm2);

    // sheaf diffusion layers (xb lives in g_h)
    for (int l = 0; l < 2; l++) {
        sheaf_H_kernel<<<NN / 4, 256>>>(Wd1, l);
        edge_scatter_kernel<<<EE / 4, 256>>>(ei);
        xb_update_kernel<<<NN * 64 / 256, 256>>>();
    }

    // output MLP
    sgemm_bias<<<dim3(1, 313), 256>>>(h,  Wo1, bo1, t1,  NN, HD, 64, 1);
    sgemm_bias<<<dim3(1, 313), 256>>>(t1, Wo2, bo2, out, NN, 64, OD, 0);
}

// round 13
// speedup vs baseline: 3.1648x; 1.0343x over previous
#include <cuda_runtime.h>
#include <cuda_bf16.h>

#define NN   20000
#define EE   200000
#define IND  500
#define HD   256
#define OD   16
#define MHD  64

// -------- scratch (alloc-free rule: __device__ globals) --------
__device__ float g_t1[NN * 64];        // MLP hidden
__device__ float g_h [NN * HD];        // h, then xb (mutated in place)
__device__ float g_H [NN * HD];        // sheaf-transformed H per layer
__device__ float g_LH[NN * HD];        // scatter accumulator
__device__ float g_pq[NN * 128];       // [n][0:64]=p=h@Wa^T, [64:128]=q=h@Wb^T
__device__ float g_Fs[EE * 16];
__device__ float g_Ft[EE * 16];
__device__ float g_Wpq[128 * HD];      // rows 0-63 = Wa, rows 64-127 = Wb
__device__ float g_Wd2T[2 * 64 * 64];  // Wd2[l] transposed -> [f][g]
__device__ float g_zero[128];          // zero bias (BSS zero-init, never written)

// -------- weight prep --------
__global__ void prep_kernel(const float* __restrict__ Wm1,
                            const float* __restrict__ Wd2) {
    int i = blockIdx.x * blockDim.x + threadIdx.x;
    if (i < 128 * 256) {
        int r = i >> 8, k = i & 255;
        g_Wpq[i] = (r < 64) ? Wm1[r * 512 + k] : Wm1[(r - 64) * 512 + 256 + k];
    }
    if (i < 2 * 64 * 64) {
        int l = i / 4096, rr = i % 4096;
        int f = rr / 64, g = rr % 64;
        g_Wd2T[i] = Wd2[l * 4096 + g * 64 + f];
    }
}

// -------- generic C = act(A @ W^T + b), A[M,Kd], W[Nc,Kd] --------
// 64x64 tile, 256 threads, 4x4 per thread; LDS.128 inner loop.
__global__ void sgemm_bias(const float* __restrict__ A,
                           const float* __restrict__ W,
                           const float* __restrict__ bias,
                           float* __restrict__ C,
                           int M, int Kd, int Nc, int doRelu) {
    __shared__ float As[16][68];
    __shared__ float Bs[16][68];
    int t  = threadIdx.x;
    int tx = t & 15, ty = t >> 4;
    int m0 = blockIdx.y * 64, n0 = blockIdx.x * 64;
    float acc[4][4];
#pragma unroll
    for (int i = 0; i < 4; i++)
#pragma unroll
        for (int j = 0; j < 4; j++) acc[i][j] = 0.f;

    for (int k0 = 0; k0 < Kd; k0 += 16) {
#pragma unroll
        for (int i = 0; i < 4; i++) {
            int q  = t + i * 256;
            int kk = q & 15, mm = q >> 4;
            int m = m0 + mm, k = k0 + kk;
            As[kk][mm] = (m < M && k < Kd) ? A[(size_t)m * Kd + k] : 0.f;
            int n = n0 + mm;
            Bs[kk][mm] = (n < Nc && k < Kd) ? W[(size_t)n * Kd + k] : 0.f;
        }
        __syncthreads();
#pragma unroll
        for (int kk = 0; kk < 16; kk++) {
            float4 a4 = *(const float4*)&As[kk][ty * 4];
            float4 b4 = *(const float4*)&Bs[kk][tx * 4];
            float a[4] = {a4.x, a4.y, a4.z, a4.w};
            float b[4] = {b4.x, b4.y, b4.z, b4.w};
#pragma unroll
            for (int i = 0; i < 4; i++)
#pragma unroll
                for (int j = 0; j < 4; j++) acc[i][j] += a[i] * b[j];
        }
        __syncthreads();
    }
#pragma unroll
    for (int i = 0; i < 4; i++) {
        int m = m0 + ty * 4 + i;
        if (m >= M) continue;
#pragma unroll
        for (int j = 0; j < 4; j++) {
            int n = n0 + tx * 4 + j;
            if (n >= Nc) continue;
            float v = acc[i][j] + bias[n];
            if (doRelu) v = fmaxf(v, 0.f);
            C[(size_t)m * Nc + n] = v;
        }
    }
}

// -------- fused edge messages: gather pq, relu-add, project with Wm2 --------
// 8 edges/block (16 messages), 256 threads.
__global__ void edge_fused_kernel(const int* __restrict__ ei,
                                  const float* __restrict__ bm1,
                                  const float* __restrict__ Wm2,
                                  const float* __restrict__ bm2) {
    __shared__ float sm[16][68];   // relu'd message pre-activations (padded)
    __shared__ float sW[16][65];   // Wm2 (16x64, padded)
    int t  = threadIdx.x;
    int eb = blockIdx.x * 8;

#pragma unroll
    for (int q = t; q < 16 * 64; q += 256) {
        sW[q >> 6][q & 63] = Wm2[q];
    }

    {
        int msg = t >> 4, v = t & 15;
        int edge = eb + (msg >> 1);
        int second = msg & 1;
        int s = ei[edge], d = ei[EE + edge];
        int na = second ? d : s;   // p-row
        int nb = second ? s : d;   // q-row
        const float4* pq4 = (const float4*)g_pq;
        float4 pa = pq4[(size_t)na * 32 + v];
        float4 qb = pq4[(size_t)nb * 32 + 16 + v];
        float4 bb = ((const float4*)bm1)[v];
        sm[msg][v * 4 + 0] = fmaxf(pa.x + qb.x + bb.x, 0.f);
        sm[msg][v * 4 + 1] = fmaxf(pa.y + qb.y + bb.y, 0.f);
        sm[msg][v * 4 + 2] = fmaxf(pa.z + qb.z + bb.z, 0.f);
        sm[msg][v * 4 + 3] = fmaxf(pa.w + qb.w + bb.w, 0.f);
    }
    __syncthreads();

    {
        int msg = t >> 4, o = t & 15;
        float acc = bm2[o];
#pragma unroll
        for (int jj = 0; jj < 64; jj++)
            acc += sW[o][jj] * sm[msg][jj];
        int edge = eb + (msg >> 1);
        if (msg & 1) g_Ft[edge * 16 + o] = acc;
        else         g_Fs[edge * 16 + o] = acc;
    }
}

// -------- per-node sheaf transform H = (Wd1^T xb) Wd2^T; also zero LH --------
__global__ void sheaf_H_kernel(const float* __restrict__ Wd1, int l) {
    __shared__ float xbs[4][256];
    __shared__ float tmps[4][256];
    int t  = threadIdx.x;
    int nb = blockIdx.x * 4;
    int n_loc = t >> 6, f = t & 63;
    {
        float4* x4 = (float4*)xbs;
        x4[n_loc * 64 + f] = ((const float4*)g_h)[(size_t)(nb + n_loc) * 64 + f];
    }
    __syncthreads();
#pragma unroll
    for (int i = 0; i < 4; i++) {
        float acc = 0.f;
#pragma unroll
        for (int j = 0; j < 4; j++)
            acc += Wd1[l * 16 + j * 4 + i] * xbs[n_loc][j * 64 + f];
        tmps[n_loc][i * 64 + f] = acc;
    }
    __syncthreads();
    int node = nb + n_loc;
    float a0 = 0.f, a1 = 0.f, a2 = 0.f, a3 = 0.f;
#pragma unroll 8
    for (int ff = 0; ff < 64; ff++) {
        float wv = g_Wd2T[l * 4096 + ff * 64 + f];
        a0 += tmps[n_loc][ff] * wv;
        a1 += tmps[n_loc][64 + ff] * wv;
        a2 += tmps[n_loc][128 + ff] * wv;
        a3 += tmps[n_loc][192 + ff] * wv;
    }
    size_t base = (size_t)node * 256;
    g_H[base + f]       = a0;
    g_H[base + 64 + f]  = a1;
    g_H[base + 128 + f] = a2;
    g_H[base + 192 + f] = a3;
    g_LH[base + f] = 0.f; g_LH[base + 64 + f] = 0.f;
    g_LH[base + 128 + f] = 0.f; g_LH[base + 192 + f] = 0.f;
}

// -------- per-edge Bx + scatter into LH (vectorized red.v4) --------
// 4 edges/block, 64 threads/edge. Stage H rows + Bx in smem, then each
// thread owns 4 consecutive f of one j-row -> 2 red.global.add.v4.f32.
__global__ void edge_scatter_kernel(const int* __restrict__ ei) {
    __shared__ float sF[4][32];    // [edge][0:16]=Fs, [16:32]=Ft
    __shared__ float sH[4][512];   // [edge][0:256]=H[src], [256:512]=H[dst]
    __shared__ float sBx[4][256];
    int t  = threadIdx.x;
    int e0 = blockIdx.x * 4;
    if (t < 128) {
        int e_loc = t >> 5, r = t & 31;
        int edge = e0 + e_loc;
        sF[e_loc][r] = (r < 16) ? g_Fs[edge * 16 + r] : g_Ft[edge * 16 + (r - 16)];
    }
    int e_loc = t >> 6;
    int edge  = e0 + e_loc;
    int s = ei[edge], d = ei[EE + edge];
    {
        int v = t & 63;
        const float4* H4 = (const float4*)g_H;
        ((float4*)sH[e_loc])[v]      = H4[(size_t)s * 64 + v];
        ((float4*)sH[e_loc])[64 + v] = H4[(size_t)d * 64 + v];
    }
    __syncthreads();
    {
        int f = t & 63;
#pragma unroll
        for (int i = 0; i < 4; i++) {
            float a = 0.f;
#pragma unroll
            for (int j = 0; j < 4; j++)
                a += sF[e_loc][16 + i * 4 + j] * sH[e_loc][256 + j * 64 + f]
                   - sF[e_loc][i * 4 + j]      * sH[e_loc][j * 64 + f];
            sBx[e_loc][i * 64 + f] = a;
        }
    }
    __syncthreads();
    {
        int j  = (t >> 4) & 3;
        int fq = t & 15;
        float csx = 0.f, csy = 0.f, csz = 0.f, csw = 0.f;
        float ctx = 0.f, cty = 0.f, ctz = 0.f, ctw = 0.f;
#pragma unroll
        for (int i = 0; i < 4; i++) {
            float4 bx = *(const float4*)&sBx[e_loc][i * 64 + fq * 4];
            float fs = sF[e_loc][i * 4 + j];
            float ft = sF[e_loc][16 + i * 4 + j];
            csx += fs * bx.x; csy += fs * bx.y; csz += fs * bx.z; csw += fs * bx.w;
            ctx += ft * bx.x; cty += ft * bx.y; ctz += ft * bx.z; ctw += ft * bx.w;
        }
        float* ps = &g_LH[(size_t)s * 256 + j * 64 + fq * 4];
        float* pd = &g_LH[(size_t)d * 256 + j * 64 + fq * 4];
        asm volatile("red.global.add.v4.f32 [%0], {%1, %2, %3, %4};"
                     :: "l"(ps), "f"(-csx), "f"(-csy), "f"(-csz), "f"(-csw) : "memory");
        asm volatile("red.global.add.v4.f32 [%0], {%1, %2, %3, %4};"
                     :: "l"(pd), "f"(ctx), "f"(cty), "f"(ctz), "f"(ctw) : "memory");
    }
}

// -------- xb = xb - relu(LH) --------
__global__ void xb_update_kernel() {
    int i = blockIdx.x * blockDim.x + threadIdx.x;
    if (i < NN * 64) {
        float4 xv = ((float4*)g_h)[i];
        float4 lv = ((float4*)g_LH)[i];
        xv.x -= fmaxf(lv.x, 0.f);
        xv.y -= fmaxf(lv.y, 0.f);
        xv.z -= fmaxf(lv.z, 0.f);
        xv.w -= fmaxf(lv.w, 0.f);
        ((float4*)g_h)[i] = xv;
    }
}

extern "C" void kernel_launch(void* const* d_in, const int* in_sizes, int n_in,
                              void* d_out, int out_size) {
    const float* x    = (const float*)d_in[0];
    const int*   ei   = (const int*)  d_in[1];
    const float* Win1 = (const float*)d_in[2];
    const float* bin1 = (const float*)d_in[3];
    const float* Win2 = (const float*)d_in[4];
    const float* bin2 = (const float*)d_in[5];
    const float* Wm1  = (const float*)d_in[6];
    const float* bm1  = (const float*)d_in[7];
    const float* Wm2  = (const float*)d_in[8];
    const float* bm2  = (const float*)d_in[9];
    const float* Wd1  = (const float*)d_in[10];
    const float* Wd2  = (const float*)d_in[11];
    const float* Wo1  = (const float*)d_in[12];
    const float* bo1  = (const float*)d_in[13];
    const float* Wo2  = (const float*)d_in[14];
    const float* bo2  = (const float*)d_in[15];
    float* out = (float*)d_out;

    void *p_t1, *p_h, *p_pq, *p_wpq, *p_zero;
    cudaGetSymbolAddress(&p_t1,   g_t1);
    cudaGetSymbolAddress(&p_h,    g_h);
    cudaGetSymbolAddress(&p_pq,   g_pq);
    cudaGetSymbolAddress(&p_wpq,  g_Wpq);
    cudaGetSymbolAddress(&p_zero, g_zero);
    float* t1   = (float*)p_t1;
    float* h    = (float*)p_h;
    float* pq   = (float*)p_pq;
    float* wpq  = (float*)p_wpq;
    float* zero = (float*)p_zero;

    prep_kernel<<<128, 256>>>(Wm1, Wd2);

    // h = relu(x @ Win1^T + bin1) @ Win2^T + bin2
    sgemm_bias<<<dim3(1, 313), 256>>>(x,  Win1, bin1, t1, NN, IND, 64, 1);
    sgemm_bias<<<dim3(4, 313), 256>>>(t1, Win2, bin2, h,  NN, 64, HD, 0);

    // node projections: pq = h @ [Wa;Wb]^T   (20000 x 128)
    sgemm_bias<<<dim3(2, 313), 256>>>(h, wpq, zero, pq, NN, HD, 128, 0);

    // edge messages -> Fs, Ft  (gather p/q rows from L2-resident pq)
    edge_fused_kernel<<<EE / 8, 256>>>(ei, bm1, Wm2, bm2);

    // sheaf diffusion layers (xb lives in g_h)
    for (int l = 0; l < 2; l++) {
        sheaf_H_kernel<<<NN / 4, 256>>>(Wd1, l);
        edge_scatter_kernel<<<EE / 4, 256>>>(ei);
        xb_update_kernel<<<NN * 64 / 256, 256>>>();
    }

    // output MLP
    sgemm_bias<<<dim3(1, 313), 256>>>(h,  Wo1, bo1, t1,  NN, HD, 64, 1);
    sgemm_bias<<<dim3(1, 313), 256>>>(t1, Wo2, bo2, out, NN, 64, OD, 0);
}